// round 8
// baseline (speedup 1.0000x reference)
#include <cuda_runtime.h>
#include <cstdint>

#define NNODE 20000
#define NEDGE 640000
#define NREL  48
#define NBASE 12
#define FDIM  128
#define KTOT  1664   // NBASE*FDIM + FDIM
#define ZLD   1664
#define OUTW  512
#define KC    16           // K columns per SMEM stage
#define NT    (KTOT / KC)  // 104
#define SLD   20           // smem row stride in floats (16 data + 4 pad)

// ----- static scratch (allocation-free rule) -----
__device__ int   g_deg[NNODE];
__device__ int   g_cur[NNODE];
__device__ int   g_off[NNODE + 1];
__device__ int   g_se[NEDGE];                       // packed: src | (etype << 16)
__device__ float g_invc[NEDGE];
__device__ float g_z[(size_t)NNODE * ZLD];          // [N, 1664] = [z_bases | x], tf32-rounded
__device__ float g_wt[3][(size_t)FDIM * KTOT];      // W^T per layer: [128, 1664], tf32-rounded

__device__ __forceinline__ float to_tf32(float x) {
    uint32_t u; asm("cvt.rna.tf32.f32 %0, %1;" : "=r"(u) : "f"(x));
    return __uint_as_float(u);
}
// ---- packed f32x2 helpers (Blackwell FFMA2 path) ----
__device__ __forceinline__ uint64_t pk2(float a, float b) {
    uint64_t r; asm("mov.b64 %0, {%1, %2};" : "=l"(r) : "f"(a), "f"(b)); return r;
}
__device__ __forceinline__ uint64_t mul2(uint64_t a, uint64_t b) {
    uint64_t r; asm("mul.rn.f32x2 %0, %1, %2;" : "=l"(r) : "l"(a), "l"(b)); return r;
}
__device__ __forceinline__ void fma2(uint64_t& d, uint64_t a, uint64_t b) {
    asm("fma.rn.f32x2 %0, %1, %2, %0;" : "+l"(d) : "l"(a), "l"(b));
}
__device__ __forceinline__ uint64_t add2(uint64_t a, uint64_t b) {
    uint64_t r; asm("add.rn.f32x2 %0, %1, %2;" : "=l"(r) : "l"(a), "l"(b)); return r;
}
__device__ __forceinline__ void upk2(uint64_t v, float& a, float& b) {
    asm("mov.b64 {%0, %1}, %2;" : "=f"(a), "=f"(b) : "l"(v));
}

// ---------------- preprocessing ----------------

__global__ void zero_kernel() {
    int i = blockIdx.x * blockDim.x + threadIdx.x;
    if (i < NNODE) { g_deg[i] = 0; g_cur[i] = 0; }
}

__global__ void hist_kernel(const int* __restrict__ dst) {
    int e = blockIdx.x * blockDim.x + threadIdx.x;
    if (e < NEDGE) atomicAdd(&g_deg[dst[e]], 1);
}

__global__ void scan_kernel() {   // 1 block, 1024 threads
    __shared__ int s[1024];
    __shared__ int carry;
    int tid = threadIdx.x;
    if (tid == 0) carry = 0;
    __syncthreads();
    for (int base = 0; base < NNODE; base += 1024) {
        int v = (base + tid < NNODE) ? g_deg[base + tid] : 0;
        s[tid] = v;
        __syncthreads();
        for (int d = 1; d < 1024; d <<= 1) {
            int t = (tid >= d) ? s[tid - d] : 0;
            __syncthreads();
            s[tid] += t;
            __syncthreads();
        }
        if (base + tid < NNODE) g_off[base + tid] = carry + s[tid] - v;
        int total = s[1023];
        __syncthreads();
        if (tid == 0) carry += total;
        __syncthreads();
    }
    if (threadIdx.x == 0) g_off[NNODE] = NEDGE;
}

__global__ void scatter_kernel(const int* __restrict__ src,
                               const int* __restrict__ dst,
                               const int* __restrict__ et) {
    int e = blockIdx.x * blockDim.x + threadIdx.x;
    if (e < NEDGE) {
        int d = dst[e];
        int p = g_off[d] + atomicAdd(&g_cur[d], 1);
        g_se[p] = src[e] | (et[e] << 16);
    }
}

__global__ void invc_kernel() {   // one block (64 thr) per node
    __shared__ int cnt[NREL];
    int i = blockIdx.x;
    for (int t = threadIdx.x; t < NREL; t += 64) cnt[t] = 0;
    __syncthreads();
    int s = g_off[i], e = g_off[i + 1];
    for (int k = s + threadIdx.x; k < e; k += 64) atomicAdd(&cnt[g_se[k] >> 16], 1);
    __syncthreads();
    for (int k = s + threadIdx.x; k < e; k += 64)
        g_invc[k] = 1.0f / (float)cnt[g_se[k] >> 16];
}

__global__ void copy_emb_kernel(const float* __restrict__ emb, float* __restrict__ out) {
    int idx = blockIdx.x * blockDim.x + threadIdx.x;   // over N*32 float4
    if (idx < NNODE * 32) {
        int n = idx >> 5, c = (idx & 31) * 4;
        *(float4*)&out[(size_t)n * OUTW + 384 + c] =
            *(const float4*)&emb[(size_t)n * FDIM + c];
    }
}

// Build Wt[layer][n, k] = ([basis_flat; root])[k, n], rounded to tf32.
__global__ void wt_kernel(const float* __restrict__ b1, const float* __restrict__ r1,
                          const float* __restrict__ b2, const float* __restrict__ r2,
                          const float* __restrict__ b3, const float* __restrict__ r3) {
    int idx = blockIdx.x * blockDim.x + threadIdx.x;
    if (idx >= 3 * FDIM * KTOT) return;
    int l = idx / (FDIM * KTOT);
    int rem = idx % (FDIM * KTOT);
    int n = rem / KTOT, k = rem % KTOT;
    const float* bas = (l == 0) ? b1 : (l == 1) ? b2 : b3;
    const float* rt  = (l == 0) ? r1 : (l == 1) ? r2 : r3;
    float v = (k < NBASE * FDIM) ? bas[(size_t)k * FDIM + n]
                                 : rt[(size_t)(k - NBASE * FDIM) * FDIM + n];
    g_wt[l][(size_t)n * KTOT + k] = to_tf32(v);
}

// ---------------- per-layer aggregation (f32x2 packed) ----------------
// z[i, b*128 + t] = sum_{e: dst=i} comp[et_e, b] * invc_e * x[src_e, t]
// z[i, 1536 + t]  = x[i, t]      (all stores tf32-rounded for the tensor GEMM)
// z held packed over base-pairs: z2[p][j] = (z[2p][f], z[2p+1][f]), f = lane*4+j
__global__ __launch_bounds__(128) void agg_kernel(const float* __restrict__ x, int xstride,
                                                  const float* __restrict__ comp) {
    __shared__ float comp_s[NREL * NBASE];
    __shared__ uint64_t red64[3][24 * 32];   // packed partials of warps 1..3
    int i = blockIdx.x;
    int tid = threadIdx.x, lane = tid & 31, w = tid >> 5;
    for (int t = tid; t < NREL * NBASE; t += 128) comp_s[t] = comp[t];
    __syncthreads();

    uint64_t z2[6][4];
    #pragma unroll
    for (int p = 0; p < 6; p++)
        #pragma unroll
        for (int j = 0; j < 4; j++) z2[p][j] = 0ull;

    int s = g_off[i], e = g_off[i + 1];

    auto edge_upd = [&](int k) {
        int se = g_se[k];
        float ic = g_invc[k];
        int src = se & 0xFFFF, et = se >> 16;
        float4 xv = *(const float4*)(x + (size_t)src * xstride + lane * 4);
        const float* cw = &comp_s[et * NBASE];
        float4 c0 = *(const float4*)cw;
        float4 c1 = *(const float4*)(cw + 4);
        float4 c2 = *(const float4*)(cw + 8);
        uint64_t icp = pk2(ic, ic);
        uint64_t wp[6];
        wp[0] = mul2(pk2(c0.x, c0.y), icp);
        wp[1] = mul2(pk2(c0.z, c0.w), icp);
        wp[2] = mul2(pk2(c1.x, c1.y), icp);
        wp[3] = mul2(pk2(c1.z, c1.w), icp);
        wp[4] = mul2(pk2(c2.x, c2.y), icp);
        wp[5] = mul2(pk2(c2.z, c2.w), icp);
        uint64_t xp[4] = { pk2(xv.x, xv.x), pk2(xv.y, xv.y),
                           pk2(xv.z, xv.z), pk2(xv.w, xv.w) };
        #pragma unroll
        for (int p = 0; p < 6; p++)
            #pragma unroll
            for (int j = 0; j < 4; j++) fma2(z2[p][j], wp[p], xp[j]);
    };

    int k = s + w;
    for (; k + 4 < e; k += 8) {   // 2-edge unroll: both gathers in flight
        edge_upd(k);
        edge_upd(k + 4);
    }
    if (k < e) edge_upd(k);

    if (w > 0) {
        #pragma unroll
        for (int p = 0; p < 6; p++)
            #pragma unroll
            for (int j = 0; j < 4; j++)
                red64[w - 1][(p * 4 + j) * 32 + lane] = z2[p][j];
    }
    __syncthreads();
    float* zrow = g_z + (size_t)i * ZLD;
    if (w == 0) {
        #pragma unroll
        for (int p = 0; p < 6; p++) {
            float lo[4], hi[4];
            #pragma unroll
            for (int j = 0; j < 4; j++) {
                uint64_t a = z2[p][j];
                #pragma unroll
                for (int ww = 0; ww < 3; ww++)
                    a = add2(a, red64[ww][(p * 4 + j) * 32 + lane]);
                upk2(a, lo[j], hi[j]);
            }
            float4 olo = make_float4(to_tf32(lo[0]), to_tf32(lo[1]), to_tf32(lo[2]), to_tf32(lo[3]));
            float4 ohi = make_float4(to_tf32(hi[0]), to_tf32(hi[1]), to_tf32(hi[2]), to_tf32(hi[3]));
            *(float4*)&zrow[(2 * p)     * FDIM + lane * 4] = olo;
            *(float4*)&zrow[(2 * p + 1) * FDIM + lane * 4] = ohi;
        }
    } else if (w == 1) {
        float4 xv = *(const float4*)(x + (size_t)i * xstride + lane * 4);
        float4 o = make_float4(to_tf32(xv.x), to_tf32(xv.y), to_tf32(xv.z), to_tf32(xv.w));
        *(float4*)&zrow[NBASE * FDIM + lane * 4] = o;
    }
}

// ---------------- tf32 mma.sync GEMM + bias + relu ----------------
// out[:, outcol:outcol+128] = relu( g_z[N,1664] @ g_wt[layer]^T + bias )
// D[m,n] = sum_k A[m,k] * B[n,k];  A = g_z rows, B = g_wt[layer] rows (K-contiguous).
__global__ void __launch_bounds__(256) gemm_mma(int layer,
                                                const float* __restrict__ bias,
                                                float* __restrict__ out, int outcol) {
    __shared__ __align__(16) float As[2][FDIM * SLD];
    __shared__ __align__(16) float Bs[2][FDIM * SLD];

    const float* wt = g_wt[layer];
    const int tid = threadIdx.x, lane = tid & 31, wid = tid >> 5;
    const int warp_m = wid & 3, warp_n = wid >> 2;        // 4 x 2 warp grid
    const int block_row = blockIdx.x * FDIM;
    const int r = lane >> 2, c = lane & 3;

    float acc[2][8][4];
    #pragma unroll
    for (int mi = 0; mi < 2; mi++)
        #pragma unroll
        for (int ni = 0; ni < 8; ni++)
            #pragma unroll
            for (int q = 0; q < 4; q++) acc[mi][ni][q] = 0.f;

    // async copy of one KC=16 tile (A + B): 1024 x 16B chunks, 4 per thread
    auto copy_tile = [&](int t, int buf) {
        #pragma unroll
        for (int it = 0; it < 4; ++it) {
            int ch = tid + it * 256;
            int isB = ch >> 9;
            int cc = ch & 511;
            int row = cc >> 2, q = cc & 3;
            float* dstp = (isB ? Bs[buf] : As[buf]) + row * SLD + q * 4;
            uint32_t dst = (uint32_t)__cvta_generic_to_shared(dstp);
            const float* src;
            if (isB) {
                src = wt + (size_t)row * KTOT + t * KC + q * 4;
            } else {
                int gr = block_row + row; if (gr >= NNODE) gr = NNODE - 1;
                src = g_z + (size_t)gr * ZLD + t * KC + q * 4;
            }
            asm volatile("cp.async.cg.shared.global [%0], [%1], 16;"
                         :: "r"(dst), "l"(src) : "memory");
        }
        asm volatile("cp.async.commit_group;" ::: "memory");
    };

    copy_tile(0, 0);

    for (int t = 0; t < NT; ++t) {
        if (t + 1 < NT) {
            copy_tile(t + 1, (t + 1) & 1);
            asm volatile("cp.async.wait_group 1;" ::: "memory");
        } else {
            asm volatile("cp.async.wait_group 0;" ::: "memory");
        }
        __syncthreads();

        const float* A = As[t & 1];
        const float* B = Bs[t & 1];
        #pragma unroll
        for (int ks = 0; ks < 2; ++ks) {
            const int kk = ks * 8;
            uint32_t af[2][4], bf[8][2];
            #pragma unroll
            for (int mi = 0; mi < 2; mi++) {
                int m0 = warp_m * 32 + mi * 16;
                af[mi][0] = __float_as_uint(A[(m0 + r)     * SLD + kk + c]);
                af[mi][1] = __float_as_uint(A[(m0 + 8 + r) * SLD + kk + c]);
                af[mi][2] = __float_as_uint(A[(m0 + r)     * SLD + kk + 4 + c]);
                af[mi][3] = __float_as_uint(A[(m0 + 8 + r) * SLD + kk + 4 + c]);
            }
            #pragma unroll
            for (int ni = 0; ni < 8; ni++) {
                int n0 = warp_n * 64 + ni * 8;
                bf[ni][0] = __float_as_uint(B[(n0 + r) * SLD + kk + c]);
                bf[ni][1] = __float_as_uint(B[(n0 + r) * SLD + kk + 4 + c]);
            }
            #pragma unroll
            for (int mi = 0; mi < 2; mi++)
                #pragma unroll
                for (int ni = 0; ni < 8; ni++) {
                    asm volatile(
                        "mma.sync.aligned.m16n8k8.row.col.f32.tf32.tf32.f32 "
                        "{%0,%1,%2,%3}, {%4,%5,%6,%7}, {%8,%9}, {%0,%1,%2,%3};"
                        : "+f"(acc[mi][ni][0]), "+f"(acc[mi][ni][1]),
                          "+f"(acc[mi][ni][2]), "+f"(acc[mi][ni][3])
                        : "r"(af[mi][0]), "r"(af[mi][1]), "r"(af[mi][2]), "r"(af[mi][3]),
                          "r"(bf[ni][0]), "r"(bf[ni][1]));
                }
        }
        __syncthreads();
    }

    // epilogue: bias + relu, float2 stores
    #pragma unroll
    for (int mi = 0; mi < 2; mi++) {
        int row0 = block_row + warp_m * 32 + mi * 16 + r;
        #pragma unroll
        for (int ni = 0; ni < 8; ni++) {
            int col = warp_n * 64 + ni * 8 + c * 2;
            float b0 = bias[col], b1 = bias[col + 1];
            if (row0 < NNODE) {
                float2 v;
                v.x = fmaxf(acc[mi][ni][0] + b0, 0.f);
                v.y = fmaxf(acc[mi][ni][1] + b1, 0.f);
                *(float2*)&out[(size_t)row0 * OUTW + outcol + col] = v;
            }
            if (row0 + 8 < NNODE) {
                float2 v;
                v.x = fmaxf(acc[mi][ni][2] + b0, 0.f);
                v.y = fmaxf(acc[mi][ni][3] + b1, 0.f);
                *(float2*)&out[(size_t)(row0 + 8) * OUTW + outcol + col] = v;
            }
        }
    }
}

// ---------------- launch ----------------
extern "C" void kernel_launch(void* const* d_in, const int* in_sizes, int n_in,
                              void* d_out, int out_size) {
    const float* emb   = (const float*)d_in[0];
    const int* esrc    = (const int*)d_in[1];
    const int* edst    = (const int*)d_in[2];
    const int* etyp    = (const int*)d_in[3];
    const float* comp1 = (const float*)d_in[4];
    const float* bas1  = (const float*)d_in[5];
    const float* root1 = (const float*)d_in[6];
    const float* bia1  = (const float*)d_in[7];
    const float* comp2 = (const float*)d_in[8];
    const float* bas2  = (const float*)d_in[9];
    const float* root2 = (const float*)d_in[10];
    const float* bia2  = (const float*)d_in[11];
    const float* comp3 = (const float*)d_in[12];
    const float* bas3  = (const float*)d_in[13];
    const float* root3 = (const float*)d_in[14];
    const float* bia3  = (const float*)d_in[15];
    float* out = (float*)d_out;

    // preprocessing (graph is identical across layers)
    zero_kernel<<<(NNODE + 255) / 256, 256>>>();
    hist_kernel<<<(NEDGE + 255) / 256, 256>>>(edst);
    scan_kernel<<<1, 1024>>>();
    scatter_kernel<<<(NEDGE + 255) / 256, 256>>>(esrc, edst, etyp);
    invc_kernel<<<NNODE, 64>>>();
    copy_emb_kernel<<<(NNODE * 32 + 255) / 256, 256>>>(emb, out);
    wt_kernel<<<(3 * FDIM * KTOT + 255) / 256, 256>>>(bas1, root1, bas2, root2, bas3, root3);

    int gemm_blocks = (NNODE + FDIM - 1) / FDIM;   // 157

    // layer 1: x = emb (stride 128) -> out cols [256,384)
    agg_kernel<<<NNODE, 128>>>(emb, FDIM, comp1);
    gemm_mma<<<gemm_blocks, 256>>>(0, bia1, out, 256);

    // layer 2: x = out[:,256:] (stride 512) -> out cols [128,256)
    agg_kernel<<<NNODE, 128>>>(out + 256, OUTW, comp2);
    gemm_mma<<<gemm_blocks, 256>>>(1, bia2, out, 128);

    // layer 3: x = out[:,128:] (stride 512) -> out cols [0,128)
    agg_kernel<<<NNODE, 128>>>(out + 128, OUTW, comp3);
    gemm_mma<<<gemm_blocks, 256>>>(2, bia3, out, 0);
}

// round 9
// speedup vs baseline: 1.5369x; 1.5369x over previous
#include <cuda_runtime.h>
#include <cstdint>

#define NNODE 20000
#define NEDGE 640000
#define NREL  48
#define NBASE 12
#define FDIM  128
#define KTOT  1664   // NBASE*FDIM + FDIM
#define ZLD   1664
#define OUTW  512
#define KC    16           // K columns per SMEM stage (GEMM)
#define NT    (KTOT / KC)  // 104
#define SLD   20           // GEMM smem row stride in floats
#define SA    36           // agg W smem stride (floats)
#define SX    132          // agg X smem stride (floats)

// ----- static scratch (allocation-free rule) -----
__device__ int   g_deg[NNODE];
__device__ int   g_cur[NNODE];
__device__ int   g_off[NNODE + 1];
__device__ int   g_se[NEDGE];                       // packed: src | (etype << 16)
__device__ float g_invc[NEDGE];
__device__ float g_z[(size_t)NNODE * ZLD];          // [N, 1664] = [z_bases | x], tf32-rounded
__device__ float g_wt[3][(size_t)FDIM * KTOT];      // W^T per layer: [128, 1664], tf32-rounded

__device__ __forceinline__ float to_tf32(float x) {
    uint32_t u; asm("cvt.rna.tf32.f32 %0, %1;" : "=r"(u) : "f"(x));
    return __uint_as_float(u);
}
__device__ __forceinline__ uint32_t to_tf32_u(float x) {
    uint32_t u; asm("cvt.rna.tf32.f32 %0, %1;" : "=r"(u) : "f"(x));
    return u;
}

// ---------------- preprocessing ----------------

__global__ void zero_kernel() {
    int i = blockIdx.x * blockDim.x + threadIdx.x;
    if (i < NNODE) { g_deg[i] = 0; g_cur[i] = 0; }
}

__global__ void hist_kernel(const int* __restrict__ dst) {
    int e = blockIdx.x * blockDim.x + threadIdx.x;
    if (e < NEDGE) atomicAdd(&g_deg[dst[e]], 1);
}

__global__ void scan_kernel() {   // 1 block, 1024 threads
    __shared__ int s[1024];
    __shared__ int carry;
    int tid = threadIdx.x;
    if (tid == 0) carry = 0;
    __syncthreads();
    for (int base = 0; base < NNODE; base += 1024) {
        int v = (base + tid < NNODE) ? g_deg[base + tid] : 0;
        s[tid] = v;
        __syncthreads();
        for (int d = 1; d < 1024; d <<= 1) {
            int t = (tid >= d) ? s[tid - d] : 0;
            __syncthreads();
            s[tid] += t;
            __syncthreads();
        }
        if (base + tid < NNODE) g_off[base + tid] = carry + s[tid] - v;
        int total = s[1023];
        __syncthreads();
        if (tid == 0) carry += total;
        __syncthreads();
    }
    if (threadIdx.x == 0) g_off[NNODE] = NEDGE;
}

__global__ void scatter_kernel(const int* __restrict__ src,
                               const int* __restrict__ dst,
                               const int* __restrict__ et) {
    int e = blockIdx.x * blockDim.x + threadIdx.x;
    if (e < NEDGE) {
        int d = dst[e];
        int p = g_off[d] + atomicAdd(&g_cur[d], 1);
        g_se[p] = src[e] | (et[e] << 16);
    }
}

__global__ void invc_kernel() {   // one block (64 thr) per node
    __shared__ int cnt[NREL];
    int i = blockIdx.x;
    for (int t = threadIdx.x; t < NREL; t += 64) cnt[t] = 0;
    __syncthreads();
    int s = g_off[i], e = g_off[i + 1];
    for (int k = s + threadIdx.x; k < e; k += 64) atomicAdd(&cnt[g_se[k] >> 16], 1);
    __syncthreads();
    for (int k = s + threadIdx.x; k < e; k += 64)
        g_invc[k] = 1.0f / (float)cnt[g_se[k] >> 16];
}

__global__ void copy_emb_kernel(const float* __restrict__ emb, float* __restrict__ out) {
    int idx = blockIdx.x * blockDim.x + threadIdx.x;   // over N*32 float4
    if (idx < NNODE * 32) {
        int n = idx >> 5, c = (idx & 31) * 4;
        *(float4*)&out[(size_t)n * OUTW + 384 + c] =
            *(const float4*)&emb[(size_t)n * FDIM + c];
    }
}

// Build Wt[layer][n, k] = ([basis_flat; root])[k, n], rounded to tf32.
__global__ void wt_kernel(const float* __restrict__ b1, const float* __restrict__ r1,
                          const float* __restrict__ b2, const float* __restrict__ r2,
                          const float* __restrict__ b3, const float* __restrict__ r3) {
    int idx = blockIdx.x * blockDim.x + threadIdx.x;
    if (idx >= 3 * FDIM * KTOT) return;
    int l = idx / (FDIM * KTOT);
    int rem = idx % (FDIM * KTOT);
    int n = rem / KTOT, k = rem % KTOT;
    const float* bas = (l == 0) ? b1 : (l == 1) ? b2 : b3;
    const float* rt  = (l == 0) ? r1 : (l == 1) ? r2 : r3;
    float v = (k < NBASE * FDIM) ? bas[(size_t)k * FDIM + n]
                                 : rt[(size_t)(k - NBASE * FDIM) * FDIM + n];
    g_wt[l][(size_t)n * KTOT + k] = to_tf32(v);
}

// ---------------- per-layer aggregation (tensor-core) ----------------
// Per node i:  z[b, f] = sum_k W[b, k] * X[k, f]
//   W[b, k] = comp[et_k, b] * invc_k   (zero-padded to [16, 32] per chunk)
//   X[k, f] = x[src_k, f]              (zero-filled for k >= deg in chunk)
// One CTA (128 thr, 4 warps) per node; warps split the 128 features 4 ways.
// z[i, 1536 + f] = x[i, f]  (self row).  All g_z stores tf32-rounded.
__global__ __launch_bounds__(128) void agg_mma(const float* __restrict__ x, int xstride,
                                               const float* __restrict__ comp) {
    __shared__ __align__(16) float sW[16 * SA];
    __shared__ __align__(16) float sX[32 * SX];
    __shared__ int   sSE[32];
    __shared__ float sIC[32];
    __shared__ float comp_s[NREL * NBASE];

    int i = blockIdx.x;
    int tid = threadIdx.x, lane = tid & 31, w = tid >> 5;
    const int r = lane >> 2, c = lane & 3;
    for (int t = tid; t < NREL * NBASE; t += 128) comp_s[t] = comp[t];

    float acc[4][4];   // 4 n-tiles (8 cols each) x 4 regs
    #pragma unroll
    for (int ni = 0; ni < 4; ni++)
        #pragma unroll
        for (int q = 0; q < 4; q++) acc[ni][q] = 0.f;

    int s = g_off[i], e = g_off[i + 1];

    for (int kb = s; kb < e; kb += 32) {
        int nk = min(32, e - kb);
        // stage edge metadata
        if (tid < 32) {
            if (tid < nk) { sSE[tid] = g_se[kb + tid]; sIC[tid] = g_invc[kb + tid]; }
            else          { sSE[tid] = 0;              sIC[tid] = 0.f; }
        }
        __syncthreads();

        // gather X: 1024 x 16B chunks (32 edges x 128 floats), zfill for padding
        #pragma unroll
        for (int it = 0; it < 8; ++it) {
            int ch = tid + it * 128;
            int ed = ch >> 5, p = ch & 31;
            uint32_t dst = (uint32_t)__cvta_generic_to_shared(&sX[ed * SX + p * 4]);
            const float* srcp = x;
            int sz = 0;
            if (ed < nk) {
                int src = sSE[ed] & 0xFFFF;
                srcp = x + (size_t)src * xstride + p * 4;
                sz = 16;
            }
            asm volatile("cp.async.cg.shared.global [%0], [%1], 16, %2;"
                         :: "r"(dst), "l"(srcp), "r"(sz) : "memory");
        }
        // build W (tf32-rounded): 16 x 32 entries
        #pragma unroll
        for (int it = 0; it < 4; ++it) {
            int idx = tid + it * 128;
            int b = idx >> 5, k = idx & 31;
            float v = 0.f;
            if (b < NBASE && k < nk) {
                int et = sSE[k] >> 16;
                v = to_tf32(comp_s[et * NBASE + b] * sIC[k]);
            }
            sW[b * SA + k] = v;
        }
        asm volatile("cp.async.commit_group;" ::: "memory");
        asm volatile("cp.async.wait_group 0;" ::: "memory");
        __syncthreads();

        // mma: M=16 (bases), N=32 per warp, K=32
        #pragma unroll
        for (int ks = 0; ks < 4; ++ks) {
            const int kk = ks * 8;
            uint32_t af0 = __float_as_uint(sW[r * SA + kk + c]);
            uint32_t af1 = __float_as_uint(sW[(r + 8) * SA + kk + c]);
            uint32_t af2 = __float_as_uint(sW[r * SA + kk + c + 4]);
            uint32_t af3 = __float_as_uint(sW[(r + 8) * SA + kk + c + 4]);
            #pragma unroll
            for (int ni = 0; ni < 4; ++ni) {
                int n0 = w * 32 + ni * 8;
                uint32_t bf0 = to_tf32_u(sX[(kk + c) * SX + n0 + r]);
                uint32_t bf1 = to_tf32_u(sX[(kk + c + 4) * SX + n0 + r]);
                asm volatile(
                    "mma.sync.aligned.m16n8k8.row.col.f32.tf32.tf32.f32 "
                    "{%0,%1,%2,%3}, {%4,%5,%6,%7}, {%8,%9}, {%0,%1,%2,%3};"
                    : "+f"(acc[ni][0]), "+f"(acc[ni][1]),
                      "+f"(acc[ni][2]), "+f"(acc[ni][3])
                    : "r"(af0), "r"(af1), "r"(af2), "r"(af3),
                      "r"(bf0), "r"(bf1));
            }
        }
        __syncthreads();   // protect sX/sW/sSE before next chunk overwrites
    }

    // epilogue: rows 0..11 of D -> g_z base rows
    float* zrow = g_z + (size_t)i * ZLD;
    #pragma unroll
    for (int ni = 0; ni < 4; ++ni) {
        int col = w * 32 + ni * 8 + c * 2;
        if (r < NBASE) {
            float2 v = make_float2(to_tf32(acc[ni][0]), to_tf32(acc[ni][1]));
            *(float2*)&zrow[r * FDIM + col] = v;
        }
        if (r + 8 < NBASE) {
            float2 v = make_float2(to_tf32(acc[ni][2]), to_tf32(acc[ni][3]));
            *(float2*)&zrow[(r + 8) * FDIM + col] = v;
        }
    }
    // self row
    if (w == 3) {
        float4 xv = *(const float4*)(x + (size_t)i * xstride + lane * 4);
        float4 o = make_float4(to_tf32(xv.x), to_tf32(xv.y), to_tf32(xv.z), to_tf32(xv.w));
        *(float4*)&zrow[NBASE * FDIM + lane * 4] = o;
    }
}

// ---------------- tf32 mma.sync GEMM + bias + relu ----------------
// out[:, outcol:outcol+128] = relu( g_z[N,1664] @ g_wt[layer]^T + bias )
__global__ void __launch_bounds__(256) gemm_mma(int layer,
                                                const float* __restrict__ bias,
                                                float* __restrict__ out, int outcol) {
    __shared__ __align__(16) float As[2][FDIM * SLD];
    __shared__ __align__(16) float Bs[2][FDIM * SLD];

    const float* wt = g_wt[layer];
    const int tid = threadIdx.x, lane = tid & 31, wid = tid >> 5;
    const int warp_m = wid & 3, warp_n = wid >> 2;        // 4 x 2 warp grid
    const int block_row = blockIdx.x * FDIM;
    const int r = lane >> 2, c = lane & 3;

    float acc[2][8][4];
    #pragma unroll
    for (int mi = 0; mi < 2; mi++)
        #pragma unroll
        for (int ni = 0; ni < 8; ni++)
            #pragma unroll
            for (int q = 0; q < 4; q++) acc[mi][ni][q] = 0.f;

    auto copy_tile = [&](int t, int buf) {
        #pragma unroll
        for (int it = 0; it < 4; ++it) {
            int ch = tid + it * 256;
            int isB = ch >> 9;
            int cc = ch & 511;
            int row = cc >> 2, q = cc & 3;
            float* dstp = (isB ? Bs[buf] : As[buf]) + row * SLD + q * 4;
            uint32_t dst = (uint32_t)__cvta_generic_to_shared(dstp);
            const float* src;
            if (isB) {
                src = wt + (size_t)row * KTOT + t * KC + q * 4;
            } else {
                int gr = block_row + row; if (gr >= NNODE) gr = NNODE - 1;
                src = g_z + (size_t)gr * ZLD + t * KC + q * 4;
            }
            asm volatile("cp.async.cg.shared.global [%0], [%1], 16;"
                         :: "r"(dst), "l"(src) : "memory");
        }
        asm volatile("cp.async.commit_group;" ::: "memory");
    };

    copy_tile(0, 0);

    for (int t = 0; t < NT; ++t) {
        if (t + 1 < NT) {
            copy_tile(t + 1, (t + 1) & 1);
            asm volatile("cp.async.wait_group 1;" ::: "memory");
        } else {
            asm volatile("cp.async.wait_group 0;" ::: "memory");
        }
        __syncthreads();

        const float* A = As[t & 1];
        const float* B = Bs[t & 1];
        #pragma unroll
        for (int ks = 0; ks < 2; ++ks) {
            const int kk = ks * 8;
            uint32_t af[2][4], bf[8][2];
            #pragma unroll
            for (int mi = 0; mi < 2; mi++) {
                int m0 = warp_m * 32 + mi * 16;
                af[mi][0] = __float_as_uint(A[(m0 + r)     * SLD + kk + c]);
                af[mi][1] = __float_as_uint(A[(m0 + 8 + r) * SLD + kk + c]);
                af[mi][2] = __float_as_uint(A[(m0 + r)     * SLD + kk + 4 + c]);
                af[mi][3] = __float_as_uint(A[(m0 + 8 + r) * SLD + kk + 4 + c]);
            }
            #pragma unroll
            for (int ni = 0; ni < 8; ni++) {
                int n0 = warp_n * 64 + ni * 8;
                bf[ni][0] = __float_as_uint(B[(n0 + r) * SLD + kk + c]);
                bf[ni][1] = __float_as_uint(B[(n0 + r) * SLD + kk + 4 + c]);
            }
            #pragma unroll
            for (int mi = 0; mi < 2; mi++)
                #pragma unroll
                for (int ni = 0; ni < 8; ni++) {
                    asm volatile(
                        "mma.sync.aligned.m16n8k8.row.col.f32.tf32.tf32.f32 "
                        "{%0,%1,%2,%3}, {%4,%5,%6,%7}, {%8,%9}, {%0,%1,%2,%3};"
                        : "+f"(acc[mi][ni][0]), "+f"(acc[mi][ni][1]),
                          "+f"(acc[mi][ni][2]), "+f"(acc[mi][ni][3])
                        : "r"(af[mi][0]), "r"(af[mi][1]), "r"(af[mi][2]), "r"(af[mi][3]),
                          "r"(bf[ni][0]), "r"(bf[ni][1]));
                }
        }
        __syncthreads();
    }

    #pragma unroll
    for (int mi = 0; mi < 2; mi++) {
        int row0 = block_row + warp_m * 32 + mi * 16 + r;
        #pragma unroll
        for (int ni = 0; ni < 8; ni++) {
            int col = warp_n * 64 + ni * 8 + c * 2;
            float b0 = bias[col], b1 = bias[col + 1];
            if (row0 < NNODE) {
                float2 v;
                v.x = fmaxf(acc[mi][ni][0] + b0, 0.f);
                v.y = fmaxf(acc[mi][ni][1] + b1, 0.f);
                *(float2*)&out[(size_t)row0 * OUTW + outcol + col] = v;
            }
            if (row0 + 8 < NNODE) {
                float2 v;
                v.x = fmaxf(acc[mi][ni][2] + b0, 0.f);
                v.y = fmaxf(acc[mi][ni][3] + b1, 0.f);
                *(float2*)&out[(size_t)(row0 + 8) * OUTW + outcol + col] = v;
            }
        }
    }
}

// ---------------- launch ----------------
extern "C" void kernel_launch(void* const* d_in, const int* in_sizes, int n_in,
                              void* d_out, int out_size) {
    const float* emb   = (const float*)d_in[0];
    const int* esrc    = (const int*)d_in[1];
    const int* edst    = (const int*)d_in[2];
    const int* etyp    = (const int*)d_in[3];
    const float* comp1 = (const float*)d_in[4];
    const float* bia1  = (const float*)d_in[7];
    const float* comp2 = (const float*)d_in[8];
    const float* bia2  = (const float*)d_in[11];
    const float* comp3 = (const float*)d_in[12];
    const float* bia3  = (const float*)d_in[15];
    const float* bas1  = (const float*)d_in[5];
    const float* root1 = (const float*)d_in[6];
    const float* bas2  = (const float*)d_in[9];
    const float* root2 = (const float*)d_in[10];
    const float* bas3  = (const float*)d_in[13];
    const float* root3 = (const float*)d_in[14];
    float* out = (float*)d_out;

    // preprocessing (graph is identical across layers)
    zero_kernel<<<(NNODE + 255) / 256, 256>>>();
    hist_kernel<<<(NEDGE + 255) / 256, 256>>>(edst);
    scan_kernel<<<1, 1024>>>();
    scatter_kernel<<<(NEDGE + 255) / 256, 256>>>(esrc, edst, etyp);
    invc_kernel<<<NNODE, 64>>>();
    copy_emb_kernel<<<(NNODE * 32 + 255) / 256, 256>>>(emb, out);
    wt_kernel<<<(3 * FDIM * KTOT + 255) / 256, 256>>>(bas1, root1, bas2, root2, bas3, root3);

    int gemm_blocks = (NNODE + FDIM - 1) / FDIM;   // 157

    // layer 1: x = emb (stride 128) -> out cols [256,384)
    agg_mma<<<NNODE, 128>>>(emb, FDIM, comp1);
    gemm_mma<<<gemm_blocks, 256>>>(0, bia1, out, 256);

    // layer 2: x = out[:,256:] (stride 512) -> out cols [128,256)
    agg_mma<<<NNODE, 128>>>(out + 256, OUTW, comp2);
    gemm_mma<<<gemm_blocks, 256>>>(1, bia2, out, 128);

    // layer 3: x = out[:,128:] (stride 512) -> out cols [0,128)
    agg_mma<<<NNODE, 128>>>(out + 128, OUTW, comp3);
    gemm_mma<<<gemm_blocks, 256>>>(2, bia3, out, 0);
}